// round 4
// baseline (speedup 1.0000x reference)
#include <cuda_runtime.h>
#include <cstdint>

#define NB   8
#define LSEQ 512
#define EDIM 1024
#define NH   16
#define HD   64

// Projected Q/K scratch (tf32-rounded f32 bits), 16 MB each.
__device__ float g_Qp[NB * LSEQ * EDIM];
__device__ float g_Kp[NB * LSEQ * EDIM];

// ---------------- helpers ----------------
static __device__ __forceinline__ uint32_t smem_u32(const void* p) {
    uint32_t a;
    asm("{ .reg .u64 t; cvta.to.shared.u64 t, %1; cvt.u32.u64 %0, t; }"
        : "=r"(a) : "l"(p));
    return a;
}
static __device__ __forceinline__ float to_tf32(float x) {
    float r; asm("cvt.rna.tf32.f32 %0, %1;" : "=f"(r) : "f"(x)); return r;
}
static __device__ __forceinline__ uint32_t ld_tf32(const float* p) {
    return __float_as_uint(to_tf32(*p));
}
static __device__ __forceinline__ float fast_ex2(float x) {
    float r; asm("ex2.approx.f32 %0, %1;" : "=f"(r) : "f"(x)); return r;
}
static __device__ __forceinline__ float fast_lg2(float x) {
    float r; asm("lg2.approx.f32 %0, %1;" : "=f"(r) : "f"(x)); return r;
}
static __device__ __forceinline__ void mma8(float c[4], const uint32_t a[4],
                                            const uint32_t b[2]) {
    asm volatile(
        "mma.sync.aligned.m16n8k8.row.col.f32.tf32.tf32.f32 "
        "{%0,%1,%2,%3},{%4,%5,%6,%7},{%8,%9},{%0,%1,%2,%3};"
        : "+f"(c[0]), "+f"(c[1]), "+f"(c[2]), "+f"(c[3])
        : "r"(a[0]), "r"(a[1]), "r"(a[2]), "r"(a[3]), "r"(b[0]), "r"(b[1]));
}
#define CP16(dst, src) \
    asm volatile("cp.async.cg.shared.global [%0], [%1], 16;" :: "r"(dst), "l"(src))
#define CP_COMMIT() asm volatile("cp.async.commit_group;")
#define CP_WAIT(n)  asm volatile("cp.async.wait_group %0;" :: "n"(n))

// ================= fused projection GEMM =================
// C[m,n] = sum_k A[m,k]*W[n,k]; blockIdx.z selects (query,W_Q)->Qp or (memory,W_K)->Kp.
// 128m x 256n block tile, KC=16, 4-stage cp.async pipeline, 8 warps (2m x 4n).
#define PPAD  20
#define PSTG  4
#define SA_ST (128 * PPAD)
#define SW_ST (256 * PPAD)
#define SW_OFF (PSTG * SA_ST)

__global__ void __launch_bounds__(256, 1)
proj_tc(const float* __restrict__ Aq, const float* __restrict__ Wq, float* __restrict__ Cq,
        const float* __restrict__ Am, const float* __restrict__ Wm, float* __restrict__ Cm) {
    extern __shared__ float sm[];
    const float* A = blockIdx.z ? Am : Aq;
    const float* W = blockIdx.z ? Wm : Wq;
    float* C       = blockIdx.z ? Cm : Cq;

    const int tid = threadIdx.x, lane = tid & 31, wid = tid >> 5;
    const int wm = wid & 1, wn = wid >> 1, g = lane >> 2, tig = lane & 3;
    const int m0 = blockIdx.y * 128, n0 = blockIdx.x * 256;
    const uint32_t smb = smem_u32(sm);

    float acc[4][8][4];
#pragma unroll
    for (int i = 0; i < 4; i++)
#pragma unroll
        for (int j = 0; j < 8; j++)
#pragma unroll
            for (int k = 0; k < 4; k++) acc[i][j][k] = 0.f;

    auto ISSUE = [&](int kc) {
        const int st = kc & 3;
        // A slab: 128 rows x 16 k  (512 cp16)
        const float* ap = A + (size_t)m0 * EDIM + kc * 16;
        uint32_t da = smb + (uint32_t)(st * SA_ST) * 4u;
#pragma unroll
        for (int s = 0; s < 2; s++) {
            int f = tid + 256 * s, row = f >> 2, c4 = (f & 3) * 4;
            CP16(da + (uint32_t)(row * PPAD + c4) * 4u,
                 ap + (size_t)row * EDIM + c4);
        }
        // W slab: 256 rows x 16 k  (1024 cp16)
        const float* wp = W + (size_t)n0 * EDIM + kc * 16;
        uint32_t dw = smb + (uint32_t)(SW_OFF + st * SW_ST) * 4u;
#pragma unroll
        for (int s = 0; s < 4; s++) {
            int f = tid + 256 * s, row = f >> 2, c4 = (f & 3) * 4;
            CP16(dw + (uint32_t)(row * PPAD + c4) * 4u,
                 wp + (size_t)row * EDIM + c4);
        }
        CP_COMMIT();
    };

#pragma unroll
    for (int s = 0; s < PSTG; s++) ISSUE(s);

    for (int kc = 0; kc < 64; kc++) {
        const int st = kc & 3;
        CP_WAIT(PSTG - 1);
        __syncthreads();
        const float* sA = sm + st * SA_ST;
        const float* sW = sm + SW_OFF + st * SW_ST;
#pragma unroll
        for (int ks = 0; ks < 2; ks++) {
            const int k0 = ks * 8;
            uint32_t af[4][4], bf[8][2];
#pragma unroll
            for (int mt = 0; mt < 4; mt++) {
                const float* base = &sA[(wm * 64 + mt * 16 + g) * PPAD + k0];
                af[mt][0] = ld_tf32(base + tig);
                af[mt][1] = ld_tf32(base + 8 * PPAD + tig);
                af[mt][2] = ld_tf32(base + tig + 4);
                af[mt][3] = ld_tf32(base + 8 * PPAD + tig + 4);
            }
#pragma unroll
            for (int nt = 0; nt < 8; nt++) {
                const float* base = &sW[(wn * 64 + nt * 8 + g) * PPAD + k0];
                bf[nt][0] = ld_tf32(base + tig);
                bf[nt][1] = ld_tf32(base + tig + 4);
            }
#pragma unroll
            for (int mt = 0; mt < 4; mt++)
#pragma unroll
                for (int nt = 0; nt < 8; nt++)
                    mma8(acc[mt][nt], af[mt], bf[nt]);
        }
        __syncthreads();
        if (kc + PSTG < 64) ISSUE(kc + PSTG);
    }
    // epilogue: tf32-rounded fp32 so attention mma operands are exact
#pragma unroll
    for (int mt = 0; mt < 4; mt++) {
        const int r0 = m0 + wm * 64 + mt * 16 + g;
#pragma unroll
        for (int nt = 0; nt < 8; nt++) {
            const int c0 = n0 + wn * 64 + nt * 8 + tig * 2;
            float2 v0 = make_float2(to_tf32(acc[mt][nt][0]), to_tf32(acc[mt][nt][1]));
            float2 v1 = make_float2(to_tf32(acc[mt][nt][2]), to_tf32(acc[mt][nt][3]));
            *(float2*)&C[(size_t)r0 * EDIM + c0] = v0;
            *(float2*)&C[(size_t)(r0 + 8) * EDIM + c0] = v1;
        }
    }
}

// ================= attention energies =================
// Block (kt,h,b): 512 threads, 16 warps in 4(m) x 4(n); warp tile 32q x 32k.
// K tile in smem (fragments streamed per-ks), Q streamed via cp.async x2.
#define APAD 68
#define EXS  0.1803368801111f   /* 0.125 * log2(e) */
#define AQ_OFF  (128 * APAD)
#define RED_OFF (3 * 128 * APAD)

__global__ void __launch_bounds__(512, 1)
attn_tc(const float* __restrict__ Qp, const float* __restrict__ Kp,
        float* __restrict__ out) {
    extern __shared__ float sm[];
    float* Ks  = sm;                 // 128 * APAD
    float* Qs  = sm + AQ_OFF;        // 2 * 128 * APAD
    float* red = sm + RED_OFF;       // 4 * 128
    const int tid = threadIdx.x, lane = tid & 31, wid = tid >> 5;
    const int wm = wid & 3, wn = wid >> 2, g = lane >> 2, tig = lane & 3;
    const int kt = blockIdx.x, h = blockIdx.y, b = blockIdx.z;

    // K tile 128 x 64 (already exact tf32 bits)
    {
        const float* kp = Kp + ((size_t)(b * LSEQ + kt * 128)) * EDIM + h * HD;
#pragma unroll
        for (int s = 0; s < 4; s++) {
            int f = tid + 512 * s, row = f >> 4, c4 = (f & 15) * 4;
            *(float4*)&Ks[row * APAD + c4] =
                *(const float4*)(kp + (size_t)row * EDIM + c4);
        }
    }

    const uint32_t qsb = smem_u32(Qs);
    auto ISSUE = [&](int i, int p) {
        const int qbase = (i >> 2) * LSEQ + (i & 3) * 128;
        const float* src0 = Qp + (size_t)qbase * EDIM + h * HD;
        const uint32_t dst0 = qsb + (uint32_t)p * 128 * APAD * 4;
#pragma unroll
        for (int s = 0; s < 4; s++) {
            int f = tid + 512 * s, row = f >> 4, c4 = (f & 15) * 4;
            CP16(dst0 + (uint32_t)(row * APAD + c4) * 4u,
                 src0 + (size_t)row * EDIM + c4);
        }
        CP_COMMIT();
    };

    ISSUE(0, 0);
    __syncthreads();   // Ks visible to all warps

    float energy = 0.f;
    float colsum[4][2];

    for (int i = 0; i < 32; i++) {
        const int p = i & 1;
        if (i + 1 < 32) { ISSUE(i + 1, p ^ 1); CP_WAIT(1); }
        else            { CP_WAIT(0); }
        __syncthreads();
        if ((i & 3) == 0) {
#pragma unroll
            for (int nt = 0; nt < 4; nt++) { colsum[nt][0] = 0.f; colsum[nt][1] = 0.f; }
        }
        float acc[2][4][4];
#pragma unroll
        for (int a1 = 0; a1 < 2; a1++)
#pragma unroll
            for (int a2 = 0; a2 < 4; a2++)
#pragma unroll
                for (int a3 = 0; a3 < 4; a3++) acc[a1][a2][a3] = 0.f;

        const float* qb = &Qs[p * 128 * APAD + (wm * 32 + g) * APAD];
        const float* kb = &Ks[(wn * 32 + g) * APAD];
#pragma unroll
        for (int ks = 0; ks < 8; ks++) {
            uint32_t qf[2][4], kf[4][2];
#pragma unroll
            for (int mt = 0; mt < 2; mt++) {
                const float* base = qb + mt * 16 * APAD + ks * 8;
                qf[mt][0] = __float_as_uint(base[tig]);
                qf[mt][1] = __float_as_uint(base[8 * APAD + tig]);
                qf[mt][2] = __float_as_uint(base[tig + 4]);
                qf[mt][3] = __float_as_uint(base[8 * APAD + tig + 4]);
            }
#pragma unroll
            for (int nt = 0; nt < 4; nt++) {
                const float* base = kb + nt * 8 * APAD + ks * 8;
                kf[nt][0] = __float_as_uint(base[tig]);
                kf[nt][1] = __float_as_uint(base[tig + 4]);
            }
#pragma unroll
            for (int mt = 0; mt < 2; mt++)
#pragma unroll
                for (int nt = 0; nt < 4; nt++)
                    mma8(acc[mt][nt], qf[mt], kf[nt]);
        }
        // exp + per-k-column accumulate (rows reduce thread-locally)
#pragma unroll
        for (int mt = 0; mt < 2; mt++)
#pragma unroll
            for (int nt = 0; nt < 4; nt++) {
                colsum[nt][0] += fast_ex2(acc[mt][nt][0] * EXS)
                               + fast_ex2(acc[mt][nt][2] * EXS);
                colsum[nt][1] += fast_ex2(acc[mt][nt][1] * EXS)
                               + fast_ex2(acc[mt][nt][3] * EXS);
            }
        if ((i & 3) == 3) {   // finished one 'a': reduce rows + log
#pragma unroll
            for (int nt = 0; nt < 4; nt++)
#pragma unroll
                for (int c2 = 0; c2 < 2; c2++) {
                    float v = colsum[nt][c2];
                    v += __shfl_xor_sync(0xffffffffu, v, 4);
                    v += __shfl_xor_sync(0xffffffffu, v, 8);
                    v += __shfl_xor_sync(0xffffffffu, v, 16);
                    if (g == 0)
                        red[wm * 128 + wn * 32 + nt * 8 + tig * 2 + c2] = v;
                }
            __syncthreads();
            if (tid < 128)
                energy += 0.69314718056f *
                    fast_lg2(red[tid] + red[128 + tid] + red[256 + tid] + red[384 + tid]);
        }
        __syncthreads();
    }
    if (tid < 128)
        out[((size_t)(b * NH + h)) * LSEQ + kt * 128 + tid] = energy;
}

// ================= host =================
#define P_SMEM ((PSTG * (SA_ST + SW_ST)) * 4)
#define A_SMEM ((3 * 128 * APAD + 512) * 4)

extern "C" void kernel_launch(void* const* d_in, const int* in_sizes, int n_in,
                              void* d_out, int out_size) {
    (void)in_sizes; (void)n_in; (void)out_size;
    const float* query  = (const float*)d_in[0];
    const float* memory = (const float*)d_in[1];
    const float* W_Q    = (const float*)d_in[2];
    const float* W_K    = (const float*)d_in[3];
    float* out = (float*)d_out;

    float *qp, *kp;
    cudaGetSymbolAddress((void**)&qp, g_Qp);
    cudaGetSymbolAddress((void**)&kp, g_Kp);

    cudaFuncSetAttribute(proj_tc, cudaFuncAttributeMaxDynamicSharedMemorySize, P_SMEM);
    cudaFuncSetAttribute(attn_tc, cudaFuncAttributeMaxDynamicSharedMemorySize, A_SMEM);

    dim3 gP(EDIM / 256, (NB * LSEQ) / 128, 2);   // 4 x 32 x 2 = 256 blocks
    proj_tc<<<gP, 256, P_SMEM>>>(query, W_Q, qp, memory, W_K, kp);

    dim3 gA(LSEQ / 128, NH, NB);                 // 4 x 16 x 8 = 512 blocks
    attn_tc<<<gA, 512, A_SMEM>>>(qp, kp, out);
}

// round 5
// speedup vs baseline: 1.9279x; 1.9279x over previous
#include <cuda_runtime.h>
#include <cuda_fp16.h>
#include <cstdint>

#define NB   8
#define LSEQ 512
#define EDIM 1024
#define NH   16
#define HD   64

// fp16 staging for inputs/weights and projected Q/K (halves of fp32 footprint).
__device__ __half g_qh[NB * LSEQ * EDIM];
__device__ __half g_mh[NB * LSEQ * EDIM];
__device__ __half g_wqh[EDIM * EDIM];
__device__ __half g_wkh[EDIM * EDIM];
__device__ __half g_Qp[NB * LSEQ * EDIM];
__device__ __half g_Kp[NB * LSEQ * EDIM];

// ---------------- helpers ----------------
static __device__ __forceinline__ uint32_t smem_u32(const void* p) {
    uint32_t a;
    asm("{ .reg .u64 t; cvta.to.shared.u64 t, %1; cvt.u32.u64 %0, t; }"
        : "=r"(a) : "l"(p));
    return a;
}
static __device__ __forceinline__ float fast_ex2(float x) {
    float r; asm("ex2.approx.f32 %0, %1;" : "=f"(r) : "f"(x)); return r;
}
static __device__ __forceinline__ float fast_lg2(float x) {
    float r; asm("lg2.approx.f32 %0, %1;" : "=f"(r) : "f"(x)); return r;
}
static __device__ __forceinline__ void mma16(float c[4], const uint32_t a[4],
                                             const uint32_t b[2]) {
    asm volatile(
        "mma.sync.aligned.m16n8k16.row.col.f32.f16.f16.f32 "
        "{%0,%1,%2,%3},{%4,%5,%6,%7},{%8,%9},{%0,%1,%2,%3};"
        : "+f"(c[0]), "+f"(c[1]), "+f"(c[2]), "+f"(c[3])
        : "r"(a[0]), "r"(a[1]), "r"(a[2]), "r"(a[3]), "r"(b[0]), "r"(b[1]));
}
#define LDSM4(r, addr) \
    asm volatile("ldmatrix.sync.aligned.m8n8.x4.shared.b16 {%0,%1,%2,%3},[%4];" \
        : "=r"((r)[0]), "=r"((r)[1]), "=r"((r)[2]), "=r"((r)[3]) : "r"(addr))
#define CP16(dst, src) \
    asm volatile("cp.async.cg.shared.global [%0], [%1], 16;" :: "r"(dst), "l"(src))
#define CP_COMMIT() asm volatile("cp.async.commit_group;")
#define CP_WAIT(n)  asm volatile("cp.async.wait_group %0;" :: "n"(n))

static __device__ __forceinline__ uint32_t h2bits(float a, float b) {
    __half2 h = __floats2half2_rn(a, b);
    return *reinterpret_cast<uint32_t*>(&h);
}

// ================= fp32 -> fp16 conversion pre-pass =================
__global__ void __launch_bounds__(256)
cvt_h(const float4* __restrict__ s, uint2* __restrict__ d, int n4) {
    int i = blockIdx.x * blockDim.x + threadIdx.x;
    const int stride = gridDim.x * blockDim.x;
    for (; i < n4; i += stride) {
        float4 v = s[i];
        uint2 o;
        o.x = h2bits(v.x, v.y);
        o.y = h2bits(v.z, v.w);
        d[i] = o;
    }
}

// ================= fp16 projection GEMM =================
// C[m,n] = sum_k A[m,k]*W[n,k]; A:[4096,1024]h, W:[1024,1024]h, C: half.
// 128m x 128n block tile, K-chunks of 16, 4-stage cp.async, 8 warps (2m x 4n).
#define PJST   12                 // u32 per 16-half k-row (48 B, conflict-free frags)
#define PJ_SLAB (128 * PJST)      // u32 per slab stage
#define PJ_SMEM (8 * PJ_SLAB * 4) // 4 A-stages + 4 W-stages = 48 KB

__global__ void __launch_bounds__(256, 2)
proj_h(const __half* __restrict__ Aq, const __half* __restrict__ Wq, __half* __restrict__ Cq,
       const __half* __restrict__ Am, const __half* __restrict__ Wm, __half* __restrict__ Cm) {
    extern __shared__ uint32_t su[];
    const __half* A = blockIdx.z ? Am : Aq;
    const __half* W = blockIdx.z ? Wm : Wq;
    __half* C       = blockIdx.z ? Cm : Cq;

    const int tid = threadIdx.x, lane = tid & 31, wid = tid >> 5;
    const int wm = wid & 1, wn = wid >> 1, g = lane >> 2, tig = lane & 3;
    const int m0 = blockIdx.y * 128, n0 = blockIdx.x * 128;
    const uint32_t smb = smem_u32(su);

    float acc[4][4][4];
#pragma unroll
    for (int i = 0; i < 4; i++)
#pragma unroll
        for (int j = 0; j < 4; j++)
#pragma unroll
            for (int k = 0; k < 4; k++) acc[i][j][k] = 0.f;

    const int crow = tid >> 1, cc = tid & 1;   // cp.async assignment
    auto ISSUE = [&](int kc) {
        const int st = kc & 3;
        CP16(smb + (uint32_t)(st * PJ_SLAB + crow * PJST + cc * 4) * 4u,
             A + (size_t)(m0 + crow) * EDIM + kc * 16 + cc * 8);
        CP16(smb + (uint32_t)((4 + st) * PJ_SLAB + crow * PJST + cc * 4) * 4u,
             W + (size_t)(n0 + crow) * EDIM + kc * 16 + cc * 8);
        CP_COMMIT();
    };
#pragma unroll
    for (int s = 0; s < 4; s++) ISSUE(s);

    for (int kc = 0; kc < 64; kc++) {
        const int st = kc & 3;
        CP_WAIT(3);
        __syncthreads();
        const uint32_t* sA = su + st * PJ_SLAB;
        const uint32_t* sW = su + (4 + st) * PJ_SLAB;
        uint32_t af[4][4], bf[4][2];
#pragma unroll
        for (int mt = 0; mt < 4; mt++) {
            const int r = (wm * 64 + mt * 16 + g) * PJST;
            af[mt][0] = sA[r + tig];
            af[mt][1] = sA[r + 8 * PJST + tig];
            af[mt][2] = sA[r + tig + 4];
            af[mt][3] = sA[r + 8 * PJST + tig + 4];
        }
#pragma unroll
        for (int nt = 0; nt < 4; nt++) {
            const int r = (wn * 32 + nt * 8 + g) * PJST;
            bf[nt][0] = sW[r + tig];
            bf[nt][1] = sW[r + tig + 4];
        }
#pragma unroll
        for (int mt = 0; mt < 4; mt++)
#pragma unroll
            for (int nt = 0; nt < 4; nt++)
                mma16(acc[mt][nt], af[mt], bf[nt]);
        __syncthreads();
        if (kc + 4 < 64) ISSUE(kc + 4);
    }
    // epilogue: fp32 acc -> packed half2 stores
    uint32_t* Cu = reinterpret_cast<uint32_t*>(C);
#pragma unroll
    for (int mt = 0; mt < 4; mt++) {
        const int row = m0 + wm * 64 + mt * 16 + g;
#pragma unroll
        for (int nt = 0; nt < 4; nt++) {
            const int colu = (n0 + wn * 32 + nt * 8) / 2 + tig;
            Cu[(size_t)row * (EDIM / 2) + colu]       = h2bits(acc[mt][nt][0], acc[mt][nt][1]);
            Cu[(size_t)(row + 8) * (EDIM / 2) + colu] = h2bits(acc[mt][nt][2], acc[mt][nt][3]);
        }
    }
}

// ================= fp16 attention energies =================
// Block (kt64, h, b): 256 thr, 8 warps (4m x 2n), warp tile 32q x 32k.
// K-tile fragments hoisted in 32 regs; Q streams via 3-stage cp.async;
// Q fragments via ldmatrix.x4. out[b,h,k] = sum_a ln(sum_q exp(0.125*dot)).
#define KST    36                  // u32 per 64-half d-row (144 B)
#define KS_OFF 0                   // 64 * 36 = 2304 u32
#define QS_OFF 2304
#define QS_ST  (128 * KST)         // 4608 u32 per stage
#define RED_OFF (QS_OFF + 3 * QS_ST)   // 16128
#define AT_SMEM (16384 * 4)        // 64 KB
#define EXS 0.1803368801111f       /* 0.125 * log2(e) */

__global__ void __launch_bounds__(256, 2)
attn_h(const __half* __restrict__ Qp, const __half* __restrict__ Kp,
       float* __restrict__ out) {
    extern __shared__ uint32_t su[];
    const int tid = threadIdx.x, lane = tid & 31, wid = tid >> 5;
    const int wm = wid & 3, wn = wid >> 2, g = lane >> 2, tig = lane & 3;
    const int kt = blockIdx.x, h = blockIdx.y, b = blockIdx.z;
    const uint32_t smb = smem_u32(su);
    float* red = reinterpret_cast<float*>(su + RED_OFF);

    // K tile 64 k-rows x 64 d (group 0)
#pragma unroll
    for (int s = 0; s < 2; s++) {
        const int f = tid + 256 * s, row = f >> 3, c = f & 7;
        CP16(smb + (uint32_t)(KS_OFF + row * KST + c * 4) * 4u,
             Kp + (size_t)(b * LSEQ + kt * 64 + row) * EDIM + h * HD + c * 8);
    }
    CP_COMMIT();

    auto ISSUE = [&](int i) {
        const int a = i >> 2, qt = i & 3, st = i % 3;
        const __half* src0 = Qp + (size_t)(a * LSEQ + qt * 128) * EDIM + h * HD;
        const uint32_t d0 = smb + (uint32_t)(QS_OFF + st * QS_ST) * 4u;
#pragma unroll
        for (int s = 0; s < 4; s++) {
            const int f = tid + 256 * s, row = f >> 3, c = f & 7;
            CP16(d0 + (uint32_t)(row * KST + c * 4) * 4u,
                 src0 + (size_t)row * EDIM + c * 8);
        }
        CP_COMMIT();
    };
    ISSUE(0);
    ISSUE(1);

    CP_WAIT(2);            // K tile done
    __syncthreads();

    // Hoist K fragments (B operand): kf[nt][ks][2]
    uint32_t kf[4][4][2];
#pragma unroll
    for (int nt = 0; nt < 4; nt++)
#pragma unroll
        for (int ks = 0; ks < 4; ks++) {
            const int r = KS_OFF + (wn * 32 + nt * 8 + g) * KST + ks * 8;
            kf[nt][ks][0] = su[r + tig];
            kf[nt][ks][1] = su[r + tig + 4];
        }

    // ldmatrix per-thread row offsets for Q fragments (2 m-tiles of 16)
    const int lrow = (lane & 7) + 8 * ((lane >> 3) & 1);
    const int lc4  = (lane >> 4) * 4;
    uint32_t qoff[2];
#pragma unroll
    for (int mt = 0; mt < 2; mt++)
        qoff[mt] = (uint32_t)((wm * 32 + mt * 16 + lrow) * KST + lc4) * 4u;

    float energy = 0.f;
    float colsum[4][2];

    for (int i = 0; i < 32; i++) {
        if (i < 31) { CP_WAIT(1); } else { CP_WAIT(0); }
        __syncthreads();
        if (i <= 29) ISSUE(i + 2);   // stage (i+2)%3 == (i-1)%3: free after barrier

        const uint32_t qs = smb + (uint32_t)(QS_OFF + (i % 3) * QS_ST) * 4u;
        if ((i & 3) == 0) {
#pragma unroll
            for (int nt = 0; nt < 4; nt++) { colsum[nt][0] = 0.f; colsum[nt][1] = 0.f; }
        }
        float acc[2][4][4];
#pragma unroll
        for (int a1 = 0; a1 < 2; a1++)
#pragma unroll
            for (int a2 = 0; a2 < 4; a2++)
#pragma unroll
                for (int a3 = 0; a3 < 4; a3++) acc[a1][a2][a3] = 0.f;

#pragma unroll
        for (int ks = 0; ks < 4; ks++) {
            uint32_t qf[2][4];
#pragma unroll
            for (int mt = 0; mt < 2; mt++)
                LDSM4(qf[mt], qs + qoff[mt] + ks * 32);
#pragma unroll
            for (int mt = 0; mt < 2; mt++)
#pragma unroll
                for (int nt = 0; nt < 4; nt++)
                    mma16(acc[mt][nt], qf[mt], kf[nt][ks]);
        }
        // exp + per-k-column accumulate (q-rows reduce thread-locally)
#pragma unroll
        for (int mt = 0; mt < 2; mt++)
#pragma unroll
            for (int nt = 0; nt < 4; nt++) {
                colsum[nt][0] += fast_ex2(acc[mt][nt][0] * EXS)
                               + fast_ex2(acc[mt][nt][2] * EXS);
                colsum[nt][1] += fast_ex2(acc[mt][nt][1] * EXS)
                               + fast_ex2(acc[mt][nt][3] * EXS);
            }
        if ((i & 3) == 3) {   // finished one 'a': reduce over q, take log
#pragma unroll
            for (int nt = 0; nt < 4; nt++)
#pragma unroll
                for (int c2 = 0; c2 < 2; c2++) {
                    float v = colsum[nt][c2];
                    v += __shfl_xor_sync(0xffffffffu, v, 4);
                    v += __shfl_xor_sync(0xffffffffu, v, 8);
                    v += __shfl_xor_sync(0xffffffffu, v, 16);
                    if (lane < 4)
                        red[wm * 64 + wn * 32 + nt * 8 + tig * 2 + c2] = v;
                }
            __syncthreads();
            if (tid < 64)
                energy += 0.69314718056f *
                    fast_lg2(red[tid] + red[64 + tid] + red[128 + tid] + red[192 + tid]);
        }
    }
    if (tid < 64)
        out[((size_t)(b * NH + h)) * LSEQ + kt * 64 + tid] = energy;
}

// ================= host =================
extern "C" void kernel_launch(void* const* d_in, const int* in_sizes, int n_in,
                              void* d_out, int out_size) {
    (void)in_sizes; (void)n_in; (void)out_size;
    const float* query  = (const float*)d_in[0];
    const float* memory = (const float*)d_in[1];
    const float* W_Q    = (const float*)d_in[2];
    const float* W_K    = (const float*)d_in[3];
    float* out = (float*)d_out;

    __half *qh, *mh, *wqh, *wkh, *qp, *kp;
    cudaGetSymbolAddress((void**)&qh,  g_qh);
    cudaGetSymbolAddress((void**)&mh,  g_mh);
    cudaGetSymbolAddress((void**)&wqh, g_wqh);
    cudaGetSymbolAddress((void**)&wkh, g_wkh);
    cudaGetSymbolAddress((void**)&qp,  g_Qp);
    cudaGetSymbolAddress((void**)&kp,  g_Kp);

    cudaFuncSetAttribute(proj_h, cudaFuncAttributeMaxDynamicSharedMemorySize, PJ_SMEM);
    cudaFuncSetAttribute(attn_h, cudaFuncAttributeMaxDynamicSharedMemorySize, AT_SMEM);

    const int nIn = NB * LSEQ * EDIM / 4;   // float4 count
    const int nW  = EDIM * EDIM / 4;
    cvt_h<<<1024, 256>>>((const float4*)query,  (uint2*)qh,  nIn);
    cvt_h<<<1024, 256>>>((const float4*)memory, (uint2*)mh,  nIn);
    cvt_h<<<512,  256>>>((const float4*)W_Q,    (uint2*)wqh, nW);
    cvt_h<<<512,  256>>>((const float4*)W_K,    (uint2*)wkh, nW);

    dim3 gP(EDIM / 128, (NB * LSEQ) / 128, 2);   // 8 x 32 x 2 = 512 blocks
    proj_h<<<gP, 256, PJ_SMEM>>>(qh, wqh, qp, mh, wkh, kp);

    dim3 gA(LSEQ / 64, NH, NB);                  // 8 x 16 x 8 = 1024 blocks
    attn_h<<<gA, 256, AT_SMEM>>>(qp, kp, out);
}

// round 6
// speedup vs baseline: 2.0840x; 1.0810x over previous
#include <cuda_runtime.h>
#include <cuda_fp16.h>
#include <cstdint>

#define NB   8
#define LSEQ 512
#define EDIM 1024
#define NH   16
#define HD   64

// fp16 staging for inputs/weights and projected Q/K.
__device__ __half g_qh[NB * LSEQ * EDIM];
__device__ __half g_mh[NB * LSEQ * EDIM];
__device__ __half g_wqh[EDIM * EDIM];
__device__ __half g_wkh[EDIM * EDIM];
__device__ __half g_Qp[NB * LSEQ * EDIM];
__device__ __half g_Kp[NB * LSEQ * EDIM];   // pre-scaled by 0.125*log2(e)

#define EXS 0.1803368801111f   /* 0.125 * log2(e), folded into K projection */

// ---------------- helpers ----------------
static __device__ __forceinline__ uint32_t smem_u32(const void* p) {
    uint32_t a;
    asm("{ .reg .u64 t; cvta.to.shared.u64 t, %1; cvt.u32.u64 %0, t; }"
        : "=r"(a) : "l"(p));
    return a;
}
static __device__ __forceinline__ float fast_lg2(float x) {
    float r; asm("lg2.approx.f32 %0, %1;" : "=f"(r) : "f"(x)); return r;
}
static __device__ __forceinline__ void mma16(float c[4], const uint32_t a[4],
                                             const uint32_t b[2]) {
    asm volatile(
        "mma.sync.aligned.m16n8k16.row.col.f32.f16.f16.f32 "
        "{%0,%1,%2,%3},{%4,%5,%6,%7},{%8,%9},{%0,%1,%2,%3};"
        : "+f"(c[0]), "+f"(c[1]), "+f"(c[2]), "+f"(c[3])
        : "r"(a[0]), "r"(a[1]), "r"(a[2]), "r"(a[3]), "r"(b[0]), "r"(b[1]));
}
#define LDSM4(r, addr) \
    asm volatile("ldmatrix.sync.aligned.m8n8.x4.shared.b16 {%0,%1,%2,%3},[%4];" \
        : "=r"((r)[0]), "=r"((r)[1]), "=r"((r)[2]), "=r"((r)[3]) : "r"(addr))
#define LDSM2(r, addr) \
    asm volatile("ldmatrix.sync.aligned.m8n8.x2.shared.b16 {%0,%1},[%2];" \
        : "=r"((r)[0]), "=r"((r)[1]) : "r"(addr))
#define CP16(dst, src) \
    asm volatile("cp.async.cg.shared.global [%0], [%1], 16;" :: "r"(dst), "l"(src))
#define CP_COMMIT() asm volatile("cp.async.commit_group;")
#define CP_WAIT(n)  asm volatile("cp.async.wait_group %0;" :: "n"(n))

static __device__ __forceinline__ uint32_t h2bits(float a, float b) {
    __half2 h = __floats2half2_rn(a, b);
    return *reinterpret_cast<uint32_t*>(&h);
}

// ================= fused fp32 -> fp16 conversion (single launch) =================
#define NIN4 (NB * LSEQ * EDIM / 4)   // 1048576 float4 per input tensor
#define NW4  (EDIM * EDIM / 4)        // 262144 float4 per weight

__global__ void __launch_bounds__(256)
cvt_all(const float4* __restrict__ q,  const float4* __restrict__ m,
        const float4* __restrict__ wq, const float4* __restrict__ wk,
        uint2* __restrict__ dq,  uint2* __restrict__ dm,
        uint2* __restrict__ dwq, uint2* __restrict__ dwk) {
    const int total = 2 * NIN4 + 2 * NW4;
    int i = blockIdx.x * blockDim.x + threadIdx.x;
    const int stride = gridDim.x * blockDim.x;
    for (; i < total; i += stride) {
        const float4* s; uint2* d; int j;
        if (i < NIN4)            { s = q;  d = dq;  j = i; }
        else if (i < 2 * NIN4)   { s = m;  d = dm;  j = i - NIN4; }
        else if (i < 2 * NIN4 + NW4) { s = wq; d = dwq; j = i - 2 * NIN4; }
        else                     { s = wk; d = dwk; j = i - 2 * NIN4 - NW4; }
        float4 v = s[j];
        d[j] = make_uint2(h2bits(v.x, v.y), h2bits(v.z, v.w));
    }
}

// ================= fp16 projection GEMM =================
// C[m,n] = sum_k A[m,k]*W[n,k]; 128m x 128n tile, KC=16, 4-stage cp.async,
// 8 warps (2m x 4n), fragments via ldmatrix. K output pre-scaled by EXS.
#define PJST   12                 // u32 per 16-half k-row (48 B)
#define PJ_SLAB (128 * PJST)
#define PJ_SMEM (8 * PJ_SLAB * 4) // 48 KB

__global__ void __launch_bounds__(256, 2)
proj_h(const __half* __restrict__ Aq, const __half* __restrict__ Wq, __half* __restrict__ Cq,
       const __half* __restrict__ Am, const __half* __restrict__ Wm, __half* __restrict__ Cm) {
    extern __shared__ uint32_t su[];
    const __half* A = blockIdx.z ? Am : Aq;
    const __half* W = blockIdx.z ? Wm : Wq;
    __half* C       = blockIdx.z ? Cm : Cq;
    const float osc = blockIdx.z ? EXS : 1.0f;   // fold logit scale into K

    const int tid = threadIdx.x, lane = tid & 31, wid = tid >> 5;
    const int wm = wid & 1, wn = wid >> 1, g = lane >> 2, tig = lane & 3;
    const int m0 = blockIdx.y * 128, n0 = blockIdx.x * 128;
    const uint32_t smb = smem_u32(su);

    // ldmatrix per-thread offsets (bytes)
    const int l16 = lane & 15;
    uint32_t aoff[4], boff[4];
#pragma unroll
    for (int mt = 0; mt < 4; mt++)
        aoff[mt] = (uint32_t)((wm * 64 + mt * 16 + l16) * PJST + (lane >> 4) * 4) * 4u;
#pragma unroll
    for (int nt = 0; nt < 4; nt++)
        boff[nt] = (uint32_t)((wn * 32 + nt * 8 + (l16 & 7)) * PJST + ((l16 >> 3) & 1) * 4) * 4u;

    float acc[4][4][4];
#pragma unroll
    for (int i = 0; i < 4; i++)
#pragma unroll
        for (int j = 0; j < 4; j++)
#pragma unroll
            for (int k = 0; k < 4; k++) acc[i][j][k] = 0.f;

    const int crow = tid >> 1, cc = tid & 1;
    auto ISSUE = [&](int kc) {
        const int st = kc & 3;
        CP16(smb + (uint32_t)(st * PJ_SLAB + crow * PJST + cc * 4) * 4u,
             A + (size_t)(m0 + crow) * EDIM + kc * 16 + cc * 8);
        CP16(smb + (uint32_t)((4 + st) * PJ_SLAB + crow * PJST + cc * 4) * 4u,
             W + (size_t)(n0 + crow) * EDIM + kc * 16 + cc * 8);
        CP_COMMIT();
    };
#pragma unroll
    for (int s = 0; s < 4; s++) ISSUE(s);

    for (int kc = 0; kc < 64; kc++) {
        const int st = kc & 3;
        CP_WAIT(3);
        __syncthreads();
        const uint32_t aB = smb + (uint32_t)(st * PJ_SLAB) * 4u;
        const uint32_t bB = smb + (uint32_t)((4 + st) * PJ_SLAB) * 4u;
        uint32_t af[4][4], bf[4][2];
#pragma unroll
        for (int mt = 0; mt < 4; mt++) LDSM4(af[mt], aB + aoff[mt]);
#pragma unroll
        for (int nt = 0; nt < 4; nt++) LDSM2(bf[nt], bB + boff[nt]);
#pragma unroll
        for (int mt = 0; mt < 4; mt++)
#pragma unroll
            for (int nt = 0; nt < 4; nt++)
                mma16(acc[mt][nt], af[mt], bf[nt]);
        __syncthreads();
        if (kc + 4 < 64) ISSUE(kc + 4);
    }
    // epilogue: fp32 acc (optionally scaled) -> packed half2 stores
    uint32_t* Cu = reinterpret_cast<uint32_t*>(C);
#pragma unroll
    for (int mt = 0; mt < 4; mt++) {
        const int row = m0 + wm * 64 + mt * 16 + g;
#pragma unroll
        for (int nt = 0; nt < 4; nt++) {
            const int colu = (n0 + wn * 32 + nt * 8) / 2 + tig;
            Cu[(size_t)row * (EDIM / 2) + colu] =
                h2bits(acc[mt][nt][0] * osc, acc[mt][nt][1] * osc);
            Cu[(size_t)(row + 8) * (EDIM / 2) + colu] =
                h2bits(acc[mt][nt][2] * osc, acc[mt][nt][3] * osc);
        }
    }
}

// ================= fp16 attention energies =================
// Block (kt64, h, b): 256 thr, 8 warps (4m x 2n), warp tile 32q x 32k.
// K frags hoisted; Q via 3-stage cp.async + ldmatrix.
// K is pre-scaled by EXS, so exp2(logit) needs no multiply:
// out[b,h,k] = sum_a ln(sum_q exp2(scaled_dot))
#define KST    36
#define KS_OFF 0
#define QS_OFF 2304
#define QS_ST  (128 * KST)
#define RED_OFF (QS_OFF + 3 * QS_ST)
#define AT_SMEM (16384 * 4)

__global__ void __launch_bounds__(256, 2)
attn_h(const __half* __restrict__ Qp, const __half* __restrict__ Kp,
       float* __restrict__ out) {
    extern __shared__ uint32_t su[];
    const int tid = threadIdx.x, lane = tid & 31, wid = tid >> 5;
    const int wm = wid & 3, wn = wid >> 2, g = lane >> 2, tig = lane & 3;
    const int kt = blockIdx.x, h = blockIdx.y, b = blockIdx.z;
    const uint32_t smb = smem_u32(su);
    float* red = reinterpret_cast<float*>(su + RED_OFF);

    // K tile 64 k-rows x 64 d
#pragma unroll
    for (int s = 0; s < 2; s++) {
        const int f = tid + 256 * s, row = f >> 3, c = f & 7;
        CP16(smb + (uint32_t)(KS_OFF + row * KST + c * 4) * 4u,
             Kp + (size_t)(b * LSEQ + kt * 64 + row) * EDIM + h * HD + c * 8);
    }
    CP_COMMIT();

    auto ISSUE = [&](int i) {
        const int a = i >> 2, qt = i & 3, st = i % 3;
        const __half* src0 = Qp + (size_t)(a * LSEQ + qt * 128) * EDIM + h * HD;
        const uint32_t d0 = smb + (uint32_t)(QS_OFF + st * QS_ST) * 4u;
#pragma unroll
        for (int s = 0; s < 4; s++) {
            const int f = tid + 256 * s, row = f >> 3, c = f & 7;
            CP16(d0 + (uint32_t)(row * KST + c * 4) * 4u,
                 src0 + (size_t)row * EDIM + c * 8);
        }
        CP_COMMIT();
    };
    ISSUE(0);
    ISSUE(1);

    CP_WAIT(2);
    __syncthreads();

    // Hoist K fragments (B operand)
    uint32_t kf[4][4][2];
#pragma unroll
    for (int nt = 0; nt < 4; nt++)
#pragma unroll
        for (int ks = 0; ks < 4; ks++) {
            const int r = KS_OFF + (wn * 32 + nt * 8 + g) * KST + ks * 8;
            kf[nt][ks][0] = su[r + tig];
            kf[nt][ks][1] = su[r + tig + 4];
        }

    // ldmatrix per-thread offsets for Q fragments
    const int lrow = (lane & 7) + 8 * ((lane >> 3) & 1);
    const int lc4  = (lane >> 4) * 4;
    uint32_t qoff[2];
#pragma unroll
    for (int mt = 0; mt < 2; mt++)
        qoff[mt] = (uint32_t)((wm * 32 + mt * 16 + lrow) * KST + lc4) * 4u;

    float energy = 0.f;
    float colsum[4][2];

    for (int i = 0; i < 32; i++) {
        if (i < 31) { CP_WAIT(1); } else { CP_WAIT(0); }
        __syncthreads();
        if (i <= 29) ISSUE(i + 2);

        const uint32_t qs = smb + (uint32_t)(QS_OFF + (i % 3) * QS_ST) * 4u;
        if ((i & 3) == 0) {
#pragma unroll
            for (int nt = 0; nt < 4; nt++) { colsum[nt][0] = 0.f; colsum[nt][1] = 0.f; }
        }
        float acc[2][4][4];
#pragma unroll
        for (int a1 = 0; a1 < 2; a1++)
#pragma unroll
            for (int a2 = 0; a2 < 4; a2++)
#pragma unroll
                for (int a3 = 0; a3 < 4; a3++) acc[a1][a2][a3] = 0.f;

#pragma unroll
        for (int ks = 0; ks < 4; ks++) {
            uint32_t qf[2][4];
#pragma unroll
            for (int mt = 0; mt < 2; mt++)
                LDSM4(qf[mt], qs + qoff[mt] + ks * 32);
#pragma unroll
            for (int mt = 0; mt < 2; mt++)
#pragma unroll
                for (int nt = 0; nt < 4; nt++)
                    mma16(acc[mt][nt], qf[mt], kf[nt][ks]);
        }
        // exp2 via f16x2 MUFU (2 values per op); accumulate per k-column in f32
#pragma unroll
        for (int mt = 0; mt < 2; mt++)
#pragma unroll
            for (int nt = 0; nt < 4; nt++) {
                uint32_t p0, p1, e0, e1;
                asm("cvt.rn.f16x2.f32 %0, %1, %2;"
                    : "=r"(p0) : "f"(acc[mt][nt][0]), "f"(acc[mt][nt][2]));
                asm("cvt.rn.f16x2.f32 %0, %1, %2;"
                    : "=r"(p1) : "f"(acc[mt][nt][1]), "f"(acc[mt][nt][3]));
                asm("ex2.approx.f16x2 %0, %1;" : "=r"(e0) : "r"(p0));
                asm("ex2.approx.f16x2 %0, %1;" : "=r"(e1) : "r"(p1));
                float2 f0 = __half22float2(*reinterpret_cast<__half2*>(&e0));
                float2 f1 = __half22float2(*reinterpret_cast<__half2*>(&e1));
                colsum[nt][0] += f0.x + f0.y;
                colsum[nt][1] += f1.x + f1.y;
            }
        if ((i & 3) == 3) {   // finished one 'a': reduce over q, take log
#pragma unroll
            for (int nt = 0; nt < 4; nt++)
#pragma unroll
                for (int c2 = 0; c2 < 2; c2++) {
                    float v = colsum[nt][c2];
                    v += __shfl_xor_sync(0xffffffffu, v, 4);
                    v += __shfl_xor_sync(0xffffffffu, v, 8);
                    v += __shfl_xor_sync(0xffffffffu, v, 16);
                    if (lane < 4)
                        red[wm * 64 + wn * 32 + nt * 8 + tig * 2 + c2] = v;
                }
            __syncthreads();
            if (tid < 64)
                energy += 0.69314718056f *
                    fast_lg2(red[tid] + red[64 + tid] + red[128 + tid] + red[192 + tid]);
        }
    }
    if (tid < 64)
        out[((size_t)(b * NH + h)) * LSEQ + kt * 64 + tid] = energy;
}

// ================= host =================
extern "C" void kernel_launch(void* const* d_in, const int* in_sizes, int n_in,
                              void* d_out, int out_size) {
    (void)in_sizes; (void)n_in; (void)out_size;
    const float* query  = (const float*)d_in[0];
    const float* memory = (const float*)d_in[1];
    const float* W_Q    = (const float*)d_in[2];
    const float* W_K    = (const float*)d_in[3];
    float* out = (float*)d_out;

    __half *qh, *mh, *wqh, *wkh, *qp, *kp;
    cudaGetSymbolAddress((void**)&qh,  g_qh);
    cudaGetSymbolAddress((void**)&mh,  g_mh);
    cudaGetSymbolAddress((void**)&wqh, g_wqh);
    cudaGetSymbolAddress((void**)&wkh, g_wkh);
    cudaGetSymbolAddress((void**)&qp,  g_Qp);
    cudaGetSymbolAddress((void**)&kp,  g_Kp);

    cudaFuncSetAttribute(proj_h, cudaFuncAttributeMaxDynamicSharedMemorySize, PJ_SMEM);
    cudaFuncSetAttribute(attn_h, cudaFuncAttributeMaxDynamicSharedMemorySize, AT_SMEM);

    cvt_all<<<2368, 256>>>((const float4*)query, (const float4*)memory,
                           (const float4*)W_Q,   (const float4*)W_K,
                           (uint2*)qh, (uint2*)mh, (uint2*)wqh, (uint2*)wkh);

    dim3 gP(EDIM / 128, (NB * LSEQ) / 128, 2);   // 8 x 32 x 2 = 512 blocks
    proj_h<<<gP, 256, PJ_SMEM>>>(qh, wqh, qp, mh, wkh, kp);

    dim3 gA(LSEQ / 64, NH, NB);                  // 8 x 16 x 8 = 1024 blocks
    attn_h<<<gA, 256, AT_SMEM>>>(qp, kp, out);
}

// round 7
// speedup vs baseline: 2.4633x; 1.1820x over previous
#include <cuda_runtime.h>
#include <cuda_fp16.h>
#include <cstdint>

#define NB   8
#define LSEQ 512
#define EDIM 1024
#define NH   16
#define HD   64

// fp16 staging for inputs/weights and projected Q/K.
__device__ __half g_qh[NB * LSEQ * EDIM];
__device__ __half g_mh[NB * LSEQ * EDIM];
__device__ __half g_wqh[EDIM * EDIM];
__device__ __half g_wkh[EDIM * EDIM];
__device__ __half g_Qp[NB * LSEQ * EDIM];
__device__ __half g_Kp[NB * LSEQ * EDIM];   // pre-scaled by 0.125*log2(e)

#define EXS 0.1803368801111f   /* 0.125 * log2(e), folded into K projection */

// ---------------- helpers ----------------
static __device__ __forceinline__ uint32_t smem_u32(const void* p) {
    uint32_t a;
    asm("{ .reg .u64 t; cvta.to.shared.u64 t, %1; cvt.u32.u64 %0, t; }"
        : "=r"(a) : "l"(p));
    return a;
}
static __device__ __forceinline__ float fast_lg2(float x) {
    float r; asm("lg2.approx.f32 %0, %1;" : "=f"(r) : "f"(x)); return r;
}
// f32-accumulate mma (projection)
static __device__ __forceinline__ void mma16(float c[4], const uint32_t a[4],
                                             const uint32_t b[2]) {
    asm volatile(
        "mma.sync.aligned.m16n8k16.row.col.f32.f16.f16.f32 "
        "{%0,%1,%2,%3},{%4,%5,%6,%7},{%8,%9},{%0,%1,%2,%3};"
        : "+f"(c[0]), "+f"(c[1]), "+f"(c[2]), "+f"(c[3])
        : "r"(a[0]), "r"(a[1]), "r"(a[2]), "r"(a[3]), "r"(b[0]), "r"(b[1]));
}
// f16-accumulate mma (attention): D packs adjacent columns per u32
static __device__ __forceinline__ void mma16h(uint32_t c[2], const uint32_t a[4],
                                              const uint32_t b[2]) {
    asm volatile(
        "mma.sync.aligned.m16n8k16.row.col.f16.f16.f16.f16 "
        "{%0,%1},{%2,%3,%4,%5},{%6,%7},{%0,%1};"
        : "+r"(c[0]), "+r"(c[1])
        : "r"(a[0]), "r"(a[1]), "r"(a[2]), "r"(a[3]), "r"(b[0]), "r"(b[1]));
}
static __device__ __forceinline__ uint32_t ex2h2(uint32_t x) {
    uint32_t r; asm("ex2.approx.f16x2 %0, %1;" : "=r"(r) : "r"(x)); return r;
}
static __device__ __forceinline__ uint32_t hadd2u(uint32_t a, uint32_t b) {
    uint32_t r; asm("add.rn.f16x2 %0, %1, %2;" : "=r"(r) : "r"(a), "r"(b)); return r;
}
#define LDSM4(r, addr) \
    asm volatile("ldmatrix.sync.aligned.m8n8.x4.shared.b16 {%0,%1,%2,%3},[%4];" \
        : "=r"((r)[0]), "=r"((r)[1]), "=r"((r)[2]), "=r"((r)[3]) : "r"(addr))
#define LDSM2(r, addr) \
    asm volatile("ldmatrix.sync.aligned.m8n8.x2.shared.b16 {%0,%1},[%2];" \
        : "=r"((r)[0]), "=r"((r)[1]) : "r"(addr))
#define CP16(dst, src) \
    asm volatile("cp.async.cg.shared.global [%0], [%1], 16;" :: "r"(dst), "l"(src))
#define CP_COMMIT() asm volatile("cp.async.commit_group;")
#define CP_WAIT(n)  asm volatile("cp.async.wait_group %0;" :: "n"(n))

static __device__ __forceinline__ uint32_t h2bits(float a, float b) {
    __half2 h = __floats2half2_rn(a, b);
    return *reinterpret_cast<uint32_t*>(&h);
}

// ================= fused fp32 -> fp16 conversion (single launch) =================
#define NIN4 (NB * LSEQ * EDIM / 4)
#define NW4  (EDIM * EDIM / 4)

__global__ void __launch_bounds__(256)
cvt_all(const float4* __restrict__ q,  const float4* __restrict__ m,
        const float4* __restrict__ wq, const float4* __restrict__ wk,
        uint2* __restrict__ dq,  uint2* __restrict__ dm,
        uint2* __restrict__ dwq, uint2* __restrict__ dwk) {
    const int total = 2 * NIN4 + 2 * NW4;
    int i = blockIdx.x * blockDim.x + threadIdx.x;
    const int stride = gridDim.x * blockDim.x;
    for (; i < total; i += stride) {
        const float4* s; uint2* d; int j;
        if (i < NIN4)            { s = q;  d = dq;  j = i; }
        else if (i < 2 * NIN4)   { s = m;  d = dm;  j = i - NIN4; }
        else if (i < 2 * NIN4 + NW4) { s = wq; d = dwq; j = i - 2 * NIN4; }
        else                     { s = wk; d = dwk; j = i - 2 * NIN4 - NW4; }
        float4 v = s[j];
        d[j] = make_uint2(h2bits(v.x, v.y), h2bits(v.z, v.w));
    }
}

// ================= fp16 projection GEMM =================
// C[m,n] = sum_k A[m,k]*W[n,k]; 128m x 128n tile, KC=16, 4-stage cp.async
// (3 in flight, single barrier per iter), 8 warps (2m x 4n), ldmatrix frags.
#define PJST   12
#define PJ_SLAB (128 * PJST)
#define PJ_SMEM (8 * PJ_SLAB * 4) // 48 KB

__global__ void __launch_bounds__(256, 2)
proj_h(const __half* __restrict__ Aq, const __half* __restrict__ Wq, __half* __restrict__ Cq,
       const __half* __restrict__ Am, const __half* __restrict__ Wm, __half* __restrict__ Cm) {
    extern __shared__ uint32_t su[];
    const __half* A = blockIdx.z ? Am : Aq;
    const __half* W = blockIdx.z ? Wm : Wq;
    __half* C       = blockIdx.z ? Cm : Cq;
    const float osc = blockIdx.z ? EXS : 1.0f;   // fold logit scale into K

    const int tid = threadIdx.x, lane = tid & 31, wid = tid >> 5;
    const int wm = wid & 1, wn = wid >> 1, g = lane >> 2, tig = lane & 3;
    const int m0 = blockIdx.y * 128, n0 = blockIdx.x * 128;
    const uint32_t smb = smem_u32(su);

    const int l16 = lane & 15;
    uint32_t aoff[4], boff[4];
#pragma unroll
    for (int mt = 0; mt < 4; mt++)
        aoff[mt] = (uint32_t)((wm * 64 + mt * 16 + l16) * PJST + (lane >> 4) * 4) * 4u;
#pragma unroll
    for (int nt = 0; nt < 4; nt++)
        boff[nt] = (uint32_t)((wn * 32 + nt * 8 + (l16 & 7)) * PJST + ((l16 >> 3) & 1) * 4) * 4u;

    float acc[4][4][4];
#pragma unroll
    for (int i = 0; i < 4; i++)
#pragma unroll
        for (int j = 0; j < 4; j++)
#pragma unroll
            for (int k = 0; k < 4; k++) acc[i][j][k] = 0.f;

    const int crow = tid >> 1, cc = tid & 1;
    auto ISSUE = [&](int kc) {
        const int st = kc & 3;
        CP16(smb + (uint32_t)(st * PJ_SLAB + crow * PJST + cc * 4) * 4u,
             A + (size_t)(m0 + crow) * EDIM + kc * 16 + cc * 8);
        CP16(smb + (uint32_t)((4 + st) * PJ_SLAB + crow * PJST + cc * 4) * 4u,
             W + (size_t)(n0 + crow) * EDIM + kc * 16 + cc * 8);
        CP_COMMIT();
    };
    ISSUE(0); ISSUE(1); ISSUE(2);

    for (int kc = 0; kc < 64; kc++) {
        const int st = kc & 3;
        CP_WAIT(2);
        __syncthreads();
        if (kc + 3 < 64) ISSUE(kc + 3);   // writes stage consumed last iter
        const uint32_t aB = smb + (uint32_t)(st * PJ_SLAB) * 4u;
        const uint32_t bB = smb + (uint32_t)((4 + st) * PJ_SLAB) * 4u;
        uint32_t af[4][4], bf[4][2];
#pragma unroll
        for (int mt = 0; mt < 4; mt++) LDSM4(af[mt], aB + aoff[mt]);
#pragma unroll
        for (int nt = 0; nt < 4; nt++) LDSM2(bf[nt], bB + boff[nt]);
#pragma unroll
        for (int mt = 0; mt < 4; mt++)
#pragma unroll
            for (int nt = 0; nt < 4; nt++)
                mma16(acc[mt][nt], af[mt], bf[nt]);
    }
    uint32_t* Cu = reinterpret_cast<uint32_t*>(C);
#pragma unroll
    for (int mt = 0; mt < 4; mt++) {
        const int row = m0 + wm * 64 + mt * 16 + g;
#pragma unroll
        for (int nt = 0; nt < 4; nt++) {
            const int colu = (n0 + wn * 32 + nt * 8) / 2 + tig;
            Cu[(size_t)row * (EDIM / 2) + colu] =
                h2bits(acc[mt][nt][0] * osc, acc[mt][nt][1] * osc);
            Cu[(size_t)(row + 8) * (EDIM / 2) + colu] =
                h2bits(acc[mt][nt][2] * osc, acc[mt][nt][3] * osc);
        }
    }
}

// ================= fp16 attention energies =================
// Block (kt64, h, b): 256 thr, 8 warps (4m x 2n), warp tile 32q x 32k.
// f16-D mma -> logits pre-packed per column pair; exp2 via MUFU f16x2;
// all reductions in f16x2 (HADD2). K pre-scaled by EXS.
#define KST    36
#define KS_OFF 0
#define QS_OFF 2304
#define QS_ST  (128 * KST)
#define RED_OFF (QS_OFF + 3 * QS_ST)
#define AT_SMEM (16384 * 4)

__global__ void __launch_bounds__(256, 3)
attn_h(const __half* __restrict__ Qp, const __half* __restrict__ Kp,
       float* __restrict__ out) {
    extern __shared__ uint32_t su[];
    const int tid = threadIdx.x, lane = tid & 31, wid = tid >> 5;
    const int wm = wid & 3, wn = wid >> 2, g = lane >> 2, tig = lane & 3;
    const int kt = blockIdx.x, h = blockIdx.y, b = blockIdx.z;
    const uint32_t smb = smem_u32(su);
    uint32_t* red = su + RED_OFF;

    // K tile 64 k-rows x 64 d
#pragma unroll
    for (int s = 0; s < 2; s++) {
        const int f = tid + 256 * s, row = f >> 3, c = f & 7;
        CP16(smb + (uint32_t)(KS_OFF + row * KST + c * 4) * 4u,
             Kp + (size_t)(b * LSEQ + kt * 64 + row) * EDIM + h * HD + c * 8);
    }
    CP_COMMIT();

    auto ISSUE = [&](int i) {
        const int a = i >> 2, qt = i & 3, st = i % 3;
        const __half* src0 = Qp + (size_t)(a * LSEQ + qt * 128) * EDIM + h * HD;
        const uint32_t d0 = smb + (uint32_t)(QS_OFF + st * QS_ST) * 4u;
#pragma unroll
        for (int s = 0; s < 4; s++) {
            const int f = tid + 256 * s, row = f >> 3, c = f & 7;
            CP16(d0 + (uint32_t)(row * KST + c * 4) * 4u,
                 src0 + (size_t)row * EDIM + c * 8);
        }
        CP_COMMIT();
    };
    ISSUE(0);
    ISSUE(1);

    CP_WAIT(2);
    __syncthreads();

    // Hoist K fragments (B operand)
    uint32_t kf[4][4][2];
#pragma unroll
    for (int nt = 0; nt < 4; nt++)
#pragma unroll
        for (int ks = 0; ks < 4; ks++) {
            const int r = KS_OFF + (wn * 32 + nt * 8 + g) * KST + ks * 8;
            kf[nt][ks][0] = su[r + tig];
            kf[nt][ks][1] = su[r + tig + 4];
        }

    // ldmatrix per-thread offsets for Q fragments
    const int lrow = (lane & 7) + 8 * ((lane >> 3) & 1);
    const int lc4  = (lane >> 4) * 4;
    uint32_t qoff[2];
#pragma unroll
    for (int mt = 0; mt < 2; mt++)
        qoff[mt] = (uint32_t)((wm * 32 + mt * 16 + lrow) * KST + lc4) * 4u;

    float2 energy = make_float2(0.f, 0.f);
    uint32_t csum[4];

    for (int i = 0; i < 32; i++) {
        if (i < 31) { CP_WAIT(1); } else { CP_WAIT(0); }
        __syncthreads();
        if (i <= 29) ISSUE(i + 2);

        const uint32_t qs = smb + (uint32_t)(QS_OFF + (i % 3) * QS_ST) * 4u;
        if ((i & 3) == 0) {
#pragma unroll
            for (int nt = 0; nt < 4; nt++) csum[nt] = 0u;
        }
        uint32_t acc[2][4][2];
#pragma unroll
        for (int a1 = 0; a1 < 2; a1++)
#pragma unroll
            for (int a2 = 0; a2 < 4; a2++) { acc[a1][a2][0] = 0u; acc[a1][a2][1] = 0u; }

#pragma unroll
        for (int ks = 0; ks < 4; ks++) {
            uint32_t qf[2][4];
#pragma unroll
            for (int mt = 0; mt < 2; mt++)
                LDSM4(qf[mt], qs + qoff[mt] + ks * 32);
#pragma unroll
            for (int mt = 0; mt < 2; mt++)
#pragma unroll
                for (int nt = 0; nt < 4; nt++)
                    mma16h(acc[mt][nt], qf[mt], kf[nt][ks]);
        }
        // exp2 directly on packed f16 logits; accumulate per column pair in f16x2
#pragma unroll
        for (int mt = 0; mt < 2; mt++)
#pragma unroll
            for (int nt = 0; nt < 4; nt++) {
                uint32_t e0 = ex2h2(acc[mt][nt][0]);   // rows r   : cols c, c+1
                uint32_t e1 = ex2h2(acc[mt][nt][1]);   // rows r+8 : cols c, c+1
                csum[nt] = hadd2u(csum[nt], hadd2u(e0, e1));
            }
        if ((i & 3) == 3) {   // finished one 'a': reduce over q rows, take log
#pragma unroll
            for (int nt = 0; nt < 4; nt++) {
                uint32_t v = csum[nt];
                v = hadd2u(v, __shfl_xor_sync(0xffffffffu, v, 4));
                v = hadd2u(v, __shfl_xor_sync(0xffffffffu, v, 8));
                v = hadd2u(v, __shfl_xor_sync(0xffffffffu, v, 16));
                if (lane < 4)
                    red[wm * 32 + wn * 16 + nt * 4 + lane] = v;
            }
            __syncthreads();
            if (tid < 32) {
                uint32_t s = hadd2u(hadd2u(red[tid], red[32 + tid]),
                                    hadd2u(red[64 + tid], red[96 + tid]));
                float2 f = __half22float2(*reinterpret_cast<__half2*>(&s));
                energy.x += 0.69314718056f * fast_lg2(f.x);
                energy.y += 0.69314718056f * fast_lg2(f.y);
            }
        }
    }
    if (tid < 32)
        *reinterpret_cast<float2*>(
            &out[((size_t)(b * NH + h)) * LSEQ + kt * 64 + 2 * tid]) = energy;
}

// ================= host =================
extern "C" void kernel_launch(void* const* d_in, const int* in_sizes, int n_in,
                              void* d_out, int out_size) {
    (void)in_sizes; (void)n_in; (void)out_size;
    const float* query  = (const float*)d_in[0];
    const float* memory = (const float*)d_in[1];
    const float* W_Q    = (const float*)d_in[2];
    const float* W_K    = (const float*)d_in[3];
    float* out = (float*)d_out;

    __half *qh, *mh, *wqh, *wkh, *qp, *kp;
    cudaGetSymbolAddress((void**)&qh,  g_qh);
    cudaGetSymbolAddress((void**)&mh,  g_mh);
    cudaGetSymbolAddress((void**)&wqh, g_wqh);
    cudaGetSymbolAddress((void**)&wkh, g_wkh);
    cudaGetSymbolAddress((void**)&qp,  g_Qp);
    cudaGetSymbolAddress((void**)&kp,  g_Kp);

    cudaFuncSetAttribute(proj_h, cudaFuncAttributeMaxDynamicSharedMemorySize, PJ_SMEM);
    cudaFuncSetAttribute(attn_h, cudaFuncAttributeMaxDynamicSharedMemorySize, AT_SMEM);

    cvt_all<<<2368, 256>>>((const float4*)query, (const float4*)memory,
                           (const float4*)W_Q,   (const float4*)W_K,
                           (uint2*)qh, (uint2*)mh, (uint2*)wqh, (uint2*)wkh);

    dim3 gP(EDIM / 128, (NB * LSEQ) / 128, 2);   // 8 x 32 x 2 = 512 blocks
    proj_h<<<gP, 256, PJ_SMEM>>>(qh, wqh, qp, mh, wkh, kp);

    dim3 gA(LSEQ / 64, NH, NB);                  // 8 x 16 x 8 = 1024 blocks
    attn_h<<<gA, 256, AT_SMEM>>>(qp, kp, out);
}

// round 8
// speedup vs baseline: 2.6187x; 1.0631x over previous
#include <cuda_runtime.h>
#include <cuda_fp16.h>
#include <cstdint>

#define NB   8
#define LSEQ 512
#define EDIM 1024
#define NH   16
#define HD   64

// fp16 staging for inputs/weights and projected Q/K.
__device__ __half g_qh[NB * LSEQ * EDIM];
__device__ __half g_mh[NB * LSEQ * EDIM];
__device__ __half g_wqh[EDIM * EDIM];
__device__ __half g_wkh[EDIM * EDIM];
__device__ __half g_Qp[NB * LSEQ * EDIM];
__device__ __half g_Kp[NB * LSEQ * EDIM];   // pre-scaled by 0.125*log2(e)

#define EXS 0.1803368801111f   /* 0.125 * log2(e), folded into K projection */

// ---------------- helpers ----------------
static __device__ __forceinline__ uint32_t smem_u32(const void* p) {
    uint32_t a;
    asm("{ .reg .u64 t; cvta.to.shared.u64 t, %1; cvt.u32.u64 %0, t; }"
        : "=r"(a) : "l"(p));
    return a;
}
static __device__ __forceinline__ float fast_lg2(float x) {
    float r; asm("lg2.approx.f32 %0, %1;" : "=f"(r) : "f"(x)); return r;
}
// f32-accumulate mma (projection)
static __device__ __forceinline__ void mma16(float c[4], const uint32_t a[4],
                                             const uint32_t b[2]) {
    asm volatile(
        "mma.sync.aligned.m16n8k16.row.col.f32.f16.f16.f32 "
        "{%0,%1,%2,%3},{%4,%5,%6,%7},{%8,%9},{%0,%1,%2,%3};"
        : "+f"(c[0]), "+f"(c[1]), "+f"(c[2]), "+f"(c[3])
        : "r"(a[0]), "r"(a[1]), "r"(a[2]), "r"(a[3]), "r"(b[0]), "r"(b[1]));
}
// f16-accumulate mma (attention): D packs adjacent columns per u32
static __device__ __forceinline__ void mma16h(uint32_t c[2], const uint32_t a[4],
                                              const uint32_t b[2]) {
    asm volatile(
        "mma.sync.aligned.m16n8k16.row.col.f16.f16.f16.f16 "
        "{%0,%1},{%2,%3,%4,%5},{%6,%7},{%0,%1};"
        : "+r"(c[0]), "+r"(c[1])
        : "r"(a[0]), "r"(a[1]), "r"(a[2]), "r"(a[3]), "r"(b[0]), "r"(b[1]));
}
static __device__ __forceinline__ uint32_t ex2h2(uint32_t x) {
    uint32_t r; asm("ex2.approx.f16x2 %0, %1;" : "=r"(r) : "r"(x)); return r;
}
static __device__ __forceinline__ uint32_t hadd2u(uint32_t a, uint32_t b) {
    uint32_t r; asm("add.rn.f16x2 %0, %1, %2;" : "=r"(r) : "r"(a), "r"(b)); return r;
}
#define LDSM4(r, addr) \
    asm volatile("ldmatrix.sync.aligned.m8n8.x4.shared.b16 {%0,%1,%2,%3},[%4];" \
        : "=r"((r)[0]), "=r"((r)[1]), "=r"((r)[2]), "=r"((r)[3]) : "r"(addr))
#define LDSM2(r, addr) \
    asm volatile("ldmatrix.sync.aligned.m8n8.x2.shared.b16 {%0,%1},[%2];" \
        : "=r"((r)[0]), "=r"((r)[1]) : "r"(addr))
#define CP16(dst, src) \
    asm volatile("cp.async.cg.shared.global [%0], [%1], 16;" :: "r"(dst), "l"(src))
#define CP_COMMIT() asm volatile("cp.async.commit_group;")
#define CP_WAIT(n)  asm volatile("cp.async.wait_group %0;" :: "n"(n))

static __device__ __forceinline__ uint32_t h2bits(float a, float b) {
    __half2 h = __floats2half2_rn(a, b);
    return *reinterpret_cast<uint32_t*>(&h);
}

// ================= fused fp32 -> fp16 conversion (single launch) =================
#define NIN4 (NB * LSEQ * EDIM / 4)
#define NW4  (EDIM * EDIM / 4)

__global__ void __launch_bounds__(256)
cvt_all(const float4* __restrict__ q,  const float4* __restrict__ m,
        const float4* __restrict__ wq, const float4* __restrict__ wk,
        uint2* __restrict__ dq,  uint2* __restrict__ dm,
        uint2* __restrict__ dwq, uint2* __restrict__ dwk) {
    const int total = 2 * NIN4 + 2 * NW4;
    int i = blockIdx.x * blockDim.x + threadIdx.x;
    const int stride = gridDim.x * blockDim.x;
    for (; i < total; i += stride) {
        const float4* s; uint2* d; int j;
        if (i < NIN4)            { s = q;  d = dq;  j = i; }
        else if (i < 2 * NIN4)   { s = m;  d = dm;  j = i - NIN4; }
        else if (i < 2 * NIN4 + NW4) { s = wq; d = dwq; j = i - 2 * NIN4; }
        else                     { s = wk; d = dwk; j = i - 2 * NIN4 - NW4; }
        float4 v = s[j];
        d[j] = make_uint2(h2bits(v.x, v.y), h2bits(v.z, v.w));
    }
}

// ================= fp16 projection GEMM =================
// C[m,n] = sum_k A[m,k]*W[n,k]; 128m x 128n tile, KC=16, 4-stage cp.async
// (3 in flight, single barrier per iter), 8 warps (2m x 4n), ldmatrix frags.
#define PJST   12
#define PJ_SLAB (128 * PJST)
#define PJ_SMEM (8 * PJ_SLAB * 4) // 48 KB

__global__ void __launch_bounds__(256, 2)
proj_h(const __half* __restrict__ Aq, const __half* __restrict__ Wq, __half* __restrict__ Cq,
       const __half* __restrict__ Am, const __half* __restrict__ Wm, __half* __restrict__ Cm) {
    extern __shared__ uint32_t su[];
    const __half* A = blockIdx.z ? Am : Aq;
    const __half* W = blockIdx.z ? Wm : Wq;
    __half* C       = blockIdx.z ? Cm : Cq;
    const float osc = blockIdx.z ? EXS : 1.0f;   // fold logit scale into K

    const int tid = threadIdx.x, lane = tid & 31, wid = tid >> 5;
    const int wm = wid & 1, wn = wid >> 1, g = lane >> 2, tig = lane & 3;
    const int m0 = blockIdx.y * 128, n0 = blockIdx.x * 128;
    const uint32_t smb = smem_u32(su);

    const int l16 = lane & 15;
    uint32_t aoff[4], boff[4];
#pragma unroll
    for (int mt = 0; mt < 4; mt++)
        aoff[mt] = (uint32_t)((wm * 64 + mt * 16 + l16) * PJST + (lane >> 4) * 4) * 4u;
#pragma unroll
    for (int nt = 0; nt < 4; nt++)
        boff[nt] = (uint32_t)((wn * 32 + nt * 8 + (l16 & 7)) * PJST + ((l16 >> 3) & 1) * 4) * 4u;

    float acc[4][4][4];
#pragma unroll
    for (int i = 0; i < 4; i++)
#pragma unroll
        for (int j = 0; j < 4; j++)
#pragma unroll
            for (int k = 0; k < 4; k++) acc[i][j][k] = 0.f;

    const int crow = tid >> 1, cc = tid & 1;
    auto ISSUE = [&](int kc) {
        const int st = kc & 3;
        CP16(smb + (uint32_t)(st * PJ_SLAB + crow * PJST + cc * 4) * 4u,
             A + (size_t)(m0 + crow) * EDIM + kc * 16 + cc * 8);
        CP16(smb + (uint32_t)((4 + st) * PJ_SLAB + crow * PJST + cc * 4) * 4u,
             W + (size_t)(n0 + crow) * EDIM + kc * 16 + cc * 8);
        CP_COMMIT();
    };
    ISSUE(0); ISSUE(1); ISSUE(2);

    for (int kc = 0; kc < 64; kc++) {
        const int st = kc & 3;
        CP_WAIT(2);
        __syncthreads();
        if (kc + 3 < 64) ISSUE(kc + 3);
        const uint32_t aB = smb + (uint32_t)(st * PJ_SLAB) * 4u;
        const uint32_t bB = smb + (uint32_t)((4 + st) * PJ_SLAB) * 4u;
        uint32_t af[4][4], bf[4][2];
#pragma unroll
        for (int mt = 0; mt < 4; mt++) LDSM4(af[mt], aB + aoff[mt]);
#pragma unroll
        for (int nt = 0; nt < 4; nt++) LDSM2(bf[nt], bB + boff[nt]);
#pragma unroll
        for (int mt = 0; mt < 4; mt++)
#pragma unroll
            for (int nt = 0; nt < 4; nt++)
                mma16(acc[mt][nt], af[mt], bf[nt]);
    }
    uint32_t* Cu = reinterpret_cast<uint32_t*>(C);
#pragma unroll
    for (int mt = 0; mt < 4; mt++) {
        const int row = m0 + wm * 64 + mt * 16 + g;
#pragma unroll
        for (int nt = 0; nt < 4; nt++) {
            const int colu = (n0 + wn * 32 + nt * 8) / 2 + tig;
            Cu[(size_t)row * (EDIM / 2) + colu] =
                h2bits(acc[mt][nt][0] * osc, acc[mt][nt][1] * osc);
            Cu[(size_t)(row + 8) * (EDIM / 2) + colu] =
                h2bits(acc[mt][nt][2] * osc, acc[mt][nt][3] * osc);
        }
    }
}

// ================= fp16 attention energies (barrier-free mainloop) =================
// Block (kt64, h, b): 8 warps; warp w owns a=w entirely (512 q rows, 16 iters
// of 32 rows), private double-buffered Q slice -> NO __syncthreads in mainloop.
// K tile (64k x 64d) shared read-only after one initial barrier.
// Swizzled 128B rows (XOR), no padding. K pre-scaled by EXS -> exp2 direct.
// smem: K 8KB | Q 8 warps x 2 stages x 4KB = 64KB | red 2KB  = 74KB -> 3 blocks/SM
#define AT_K_U32  2048
#define AT_Q_U32  16384
#define AT_SMEM   ((AT_K_U32 + AT_Q_U32 + 512) * 4)

__global__ void __launch_bounds__(256, 3)
attn_h(const __half* __restrict__ Qp, const __half* __restrict__ Kp,
       float* __restrict__ out) {
    extern __shared__ uint32_t su[];
    const int tid = threadIdx.x, lane = tid & 31, wid = tid >> 5;
    const int kt = blockIdx.x, h = blockIdx.y, b = blockIdx.z;
    const uint32_t smb = smem_u32(su);
    float* red = reinterpret_cast<float*>(su + AT_K_U32 + AT_Q_U32);

    // ---- K tile: 64 k-rows x 64 halves, swizzled 128B rows ----
#pragma unroll
    for (int s = 0; s < 2; s++) {
        const int f = tid + 256 * s, row = f >> 3, ch = f & 7;
        const int swz = ch ^ (row & 7);
        CP16(smb + (uint32_t)(row * 32 + swz * 4) * 4u,
             Kp + (size_t)(b * LSEQ + kt * 64 + row) * EDIM + h * HD + ch * 8);
    }
    CP_COMMIT();

    // ---- per-warp private Q slice: 2 stages x 32 rows x 128B ----
    const uint32_t qw = smb + (uint32_t)(AT_K_U32 + wid * 2048) * 4u;
    auto ISSUE = [&](int i) {
        const __half* src = Qp + (size_t)(wid * LSEQ + i * 32) * EDIM + h * HD;
        const uint32_t d0 = qw + (uint32_t)(i & 1) * 4096u;
#pragma unroll
        for (int s = 0; s < 8; s++) {
            const int f = lane + 32 * s, row = f >> 3, ch = f & 7;
            const int swz = ch ^ (row & 7);
            CP16(d0 + (uint32_t)(row * 32 + swz * 4) * 4u,
                 src + (size_t)row * EDIM + ch * 8);
        }
        CP_COMMIT();
    };
    ISSUE(0); ISSUE(1);
    CP_WAIT(2);        // K group retired for this thread
    __syncthreads();   // K visible to all warps (only barrier before mainloop)

    // ldmatrix offsets (swizzle folded: XOR terms touch only chunk bits 4-6)
    const int l7 = lane & 7;
    const uint32_t qa_base = (uint32_t)((l7 + 8 * ((lane >> 3) & 1)) * 128
                                        + (((lane >> 4) ^ l7) * 16));
    const uint32_t ka_base = (uint32_t)(l7 * 128 + (((lane >> 3) ^ l7) * 16));

    uint32_t csum[8];
#pragma unroll
    for (int nt = 0; nt < 8; nt++) csum[nt] = 0u;

    for (int i = 0; i < 16; i++) {
        if (i < 15) { CP_WAIT(1); } else { CP_WAIT(0); }
        const uint32_t qst = qw + (uint32_t)(i & 1) * 4096u;

        uint32_t acc[2][8][2];
#pragma unroll
        for (int mt = 0; mt < 2; mt++)
#pragma unroll
            for (int nt = 0; nt < 8; nt++) { acc[mt][nt][0] = 0u; acc[mt][nt][1] = 0u; }

#pragma unroll
        for (int ksp = 0; ksp < 2; ksp++) {
            uint32_t qf[2][2][4];   // [kk][mt]
#pragma unroll
            for (int kk = 0; kk < 2; kk++)
#pragma unroll
                for (int mt = 0; mt < 2; mt++)
                    LDSM4(qf[kk][mt],
                          qst + (uint32_t)(mt * 2048)
                              + (qa_base ^ ((uint32_t)(2 * ksp + kk) << 5)));
#pragma unroll
            for (int nt = 0; nt < 8; nt++) {
                uint32_t kw[4];     // b-frags for ks=2ksp (kw[0..1]) and 2ksp+1 (kw[2..3])
                LDSM4(kw, smb + (uint32_t)(nt * 1024)
                              + (ka_base ^ ((uint32_t)ksp << 6)));
                mma16h(acc[0][nt], qf[0][0], &kw[0]);
                mma16h(acc[1][nt], qf[0][1], &kw[0]);
                mma16h(acc[0][nt], qf[1][0], &kw[2]);
                mma16h(acc[1][nt], qf[1][1], &kw[2]);
            }
        }
        if (i < 14) ISSUE(i + 2);   // prefetch into just-consumed stage

        // exp2 on packed f16 logits; accumulate per column pair in f16x2
#pragma unroll
        for (int nt = 0; nt < 8; nt++) {
            uint32_t e0 = ex2h2(acc[0][nt][0]);
            uint32_t e1 = ex2h2(acc[0][nt][1]);
            uint32_t e2 = ex2h2(acc[1][nt][0]);
            uint32_t e3 = ex2h2(acc[1][nt][1]);
            csum[nt] = hadd2u(csum[nt], hadd2u(hadd2u(e0, e1), hadd2u(e2, e3)));
        }
    }

    // per-warp: reduce over q-row groups, take log2 of sum (a = wid)
#pragma unroll
    for (int nt = 0; nt < 8; nt++) {
        uint32_t v = csum[nt];
        v = hadd2u(v, __shfl_xor_sync(0xffffffffu, v, 4));
        v = hadd2u(v, __shfl_xor_sync(0xffffffffu, v, 8));
        v = hadd2u(v, __shfl_xor_sync(0xffffffffu, v, 16));
        if (lane < 4) {
            float2 f = __half22float2(*reinterpret_cast<__half2*>(&v));
            float2 lg = make_float2(fast_lg2(f.x), fast_lg2(f.y));
            *reinterpret_cast<float2*>(&red[wid * 64 + nt * 8 + lane * 2]) = lg;
        }
    }
    __syncthreads();
    if (tid < 64) {
        float s = 0.f;
#pragma unroll
        for (int w = 0; w < 8; w++) s += red[w * 64 + tid];
        out[((size_t)(b * NH + h)) * LSEQ + kt * 64 + tid] = 0.69314718056f * s;
    }
}

// ================= host =================
extern "C" void kernel_launch(void* const* d_in, const int* in_sizes, int n_in,
                              void* d_out, int out_size) {
    (void)in_sizes; (void)n_in; (void)out_size;
    const float* query  = (const float*)d_in[0];
    const float* memory = (const float*)d_in[1];
    const float* W_Q    = (const float*)d_in[2];
    const float* W_K    = (const float*)d_in[3];
    float* out = (float*)d_out;

    __half *qh, *mh, *wqh, *wkh, *qp, *kp;
    cudaGetSymbolAddress((void**)&qh,  g_qh);
    cudaGetSymbolAddress((void**)&mh,  g_mh);
    cudaGetSymbolAddress((void**)&wqh, g_wqh);
    cudaGetSymbolAddress((void**)&wkh, g_wkh);
    cudaGetSymbolAddress((void**)&qp,  g_Qp);
    cudaGetSymbolAddress((void**)&kp,  g_Kp);

    cudaFuncSetAttribute(proj_h, cudaFuncAttributeMaxDynamicSharedMemorySize, PJ_SMEM);
    cudaFuncSetAttribute(attn_h, cudaFuncAttributeMaxDynamicSharedMemorySize, AT_SMEM);

    cvt_all<<<2368, 256>>>((const float4*)query, (const float4*)memory,
                           (const float4*)W_Q,   (const float4*)W_K,
                           (uint2*)qh, (uint2*)mh, (uint2*)wqh, (uint2*)wkh);

    dim3 gP(EDIM / 128, (NB * LSEQ) / 128, 2);   // 8 x 32 x 2 = 512 blocks
    proj_h<<<gP, 256, PJ_SMEM>>>(qh, wqh, qp, mh, wkh, kp);

    dim3 gA(LSEQ / 64, NH, NB);                  // 8 x 16 x 8 = 1024 blocks
    attn_h<<<gA, 256, AT_SMEM>>>(qp, kp, out);
}